// round 1
// baseline (speedup 1.0000x reference)
#include <cuda_runtime.h>
#include <math.h>

// ---------------- problem dims ----------------
#define B_  4
#define T_  2048
#define C_  1024
#define H_  8
#define DH_ 128
#define DFF_ 4096
#define ROWS_ (B_*T_)          // 8192

// ---------------- scratch (device globals; no allocs allowed) ----------------
__device__ float g_h[ROWS_*C_];          // LN output (reused for LN1 and LN2)
__device__ float g_q[ROWS_*C_];          // [B,H,T,Dh]
__device__ float g_k[ROWS_*C_];          // [B,H,T,Dh]
__device__ float g_v[ROWS_*C_];          // [B,H,T,Dh]
__device__ float g_scores[(long)B_*H_*T_*T_];  // 536 MB
__device__ float g_xmid[ROWS_*C_];       // x + attn_out
__device__ float g_ff1[ROWS_*DFF_];      // 128 MB

// ---------------- LayerNorm ----------------
__global__ __launch_bounds__(256) void ln_kernel(
    const float* __restrict__ x, const float* __restrict__ g,
    const float* __restrict__ b, float* __restrict__ out)
{
    long row = blockIdx.x;
    const float* p = x + row * C_;
    int tid = threadIdx.x;
    float v[4];
    float s = 0.f, s2 = 0.f;
    #pragma unroll
    for (int i = 0; i < 4; i++) {
        v[i] = p[tid + i*256];
        s += v[i]; s2 += v[i]*v[i];
    }
    __shared__ float sh[2][8];
    #pragma unroll
    for (int o = 16; o; o >>= 1) {
        s  += __shfl_xor_sync(0xffffffffu, s,  o);
        s2 += __shfl_xor_sync(0xffffffffu, s2, o);
    }
    int lane = tid & 31, w = tid >> 5;
    if (lane == 0) { sh[0][w] = s; sh[1][w] = s2; }
    __syncthreads();
    if (tid == 0) {
        float a = 0.f, c = 0.f;
        #pragma unroll
        for (int i = 0; i < 8; i++) { a += sh[0][i]; c += sh[1][i]; }
        sh[0][0] = a; sh[1][0] = c;
    }
    __syncthreads();
    float mu  = sh[0][0] * (1.f / C_);
    float var = sh[1][0] * (1.f / C_) - mu * mu;
    float rstd = rsqrtf(var + 1e-5f);
    float* o = out + row * C_;
    #pragma unroll
    for (int i = 0; i < 4; i++) {
        int n = tid + i*256;
        o[n] = (v[i] - mu) * rstd * g[n] + b[n];
    }
}

// ---------------- Softmax over last dim (2048) ----------------
__global__ __launch_bounds__(256) void softmax_kernel(float* __restrict__ sc)
{
    long row = blockIdx.x;
    float* p = sc + row * (long)T_;
    int tid = threadIdx.x;
    float v[8];
    float m = -1e30f;
    #pragma unroll
    for (int i = 0; i < 8; i++) { v[i] = p[tid + i*256]; m = fmaxf(m, v[i]); }
    __shared__ float sh[8];
    __shared__ float res;
    int lane = tid & 31, w = tid >> 5;
    #pragma unroll
    for (int o = 16; o; o >>= 1) m = fmaxf(m, __shfl_xor_sync(0xffffffffu, m, o));
    if (lane == 0) sh[w] = m;
    __syncthreads();
    if (tid == 0) {
        float a = sh[0];
        #pragma unroll
        for (int i = 1; i < 8; i++) a = fmaxf(a, sh[i]);
        res = a;
    }
    __syncthreads();
    float mm = res;
    float sum = 0.f;
    #pragma unroll
    for (int i = 0; i < 8; i++) { v[i] = __expf(v[i] - mm); sum += v[i]; }
    __syncthreads();   // protect sh reuse
    #pragma unroll
    for (int o = 16; o; o >>= 1) sum += __shfl_xor_sync(0xffffffffu, sum, o);
    if (lane == 0) sh[w] = sum;
    __syncthreads();
    if (tid == 0) {
        float a = 0.f;
        #pragma unroll
        for (int i = 0; i < 8; i++) a += sh[i];
        res = a;
    }
    __syncthreads();
    float inv = 1.f / res;
    #pragma unroll
    for (int i = 0; i < 8; i++) p[tid + i*256] = v[i] * inv;
}

// ---------------- Generic batched tiled SGEMM ----------------
// C[m,n] = alpha * sum_k A[m,k]*B[k,n]   (TRB=false)  or  A[m,k]*B[n,k] (TRB=true)
// batch z -> (zb = z/H, zh = z%H); per-b and per-h strides on A/B/C/res.
// Optional bias[n], relu, residual.
#define BM 64
#define BN 64
#define BKK 16

template<bool TRB, bool RELU, bool BIAS, bool RES>
__global__ __launch_bounds__(256) void gemm_kernel(
    int K,
    const float* __restrict__ A, int lda, long sAb, long sAh,
    const float* __restrict__ B, int ldb, long sBb, long sBh,
    float* __restrict__ C, int ldc, long sCb, long sCh,
    const float* __restrict__ bias,
    const float* __restrict__ res, int ldr, long sRb, long sRh,
    float alpha, int H)
{
    int z = blockIdx.z;
    int zb = z / H, zh = z - zb * H;
    A += zb * sAb + zh * sAh;
    B += zb * sBb + zh * sBh;
    C += zb * sCb + zh * sCh;
    if (RES) res += zb * sRb + zh * sRh;

    __shared__ float As[BKK][BM + 4];
    __shared__ float Bs[BKK][BN + 4];

    int m0 = blockIdx.y * BM;
    int n0 = blockIdx.x * BN;
    int tid = threadIdx.x;
    int tx = tid & 15, ty = tid >> 4;

    float acc[4][4];
    #pragma unroll
    for (int i = 0; i < 4; i++)
        #pragma unroll
        for (int j = 0; j < 4; j++) acc[i][j] = 0.f;

    for (int k0 = 0; k0 < K; k0 += BKK) {
        // load A tile (BM x BKK): thread k = tid%16, m = tid/16 (+i*16)
        {
            int k = tid & 15;
            int m = tid >> 4;
            #pragma unroll
            for (int i = 0; i < 4; i++)
                As[k][m + i*16] = A[(long)(m0 + m + i*16) * lda + (k0 + k)];
        }
        if (!TRB) {
            // B[k,n]: thread n = tid%64, k = tid/64 (+i*4)
            int n = tid & 63;
            int k = tid >> 6;
            #pragma unroll
            for (int i = 0; i < 4; i++)
                Bs[k + i*4][n] = B[(long)(k0 + k + i*4) * ldb + (n0 + n)];
        } else {
            // B[n,k]: thread k = tid%16, n = tid/16 (+i*16)
            int k = tid & 15;
            int n = tid >> 4;
            #pragma unroll
            for (int i = 0; i < 4; i++)
                Bs[k][n + i*16] = B[(long)(n0 + n + i*16) * ldb + (k0 + k)];
        }
        __syncthreads();
        #pragma unroll
        for (int k = 0; k < BKK; k++) {
            float4 a4 = *reinterpret_cast<const float4*>(&As[k][ty*4]);
            float4 b4 = *reinterpret_cast<const float4*>(&Bs[k][tx*4]);
            float a[4] = {a4.x, a4.y, a4.z, a4.w};
            float bb[4] = {b4.x, b4.y, b4.z, b4.w};
            #pragma unroll
            for (int i = 0; i < 4; i++)
                #pragma unroll
                for (int j = 0; j < 4; j++)
                    acc[i][j] += a[i] * bb[j];
        }
        __syncthreads();
    }

    #pragma unroll
    for (int i = 0; i < 4; i++) {
        int m = m0 + ty*4 + i;
        #pragma unroll
        for (int j = 0; j < 4; j++) {
            int n = n0 + tx*4 + j;
            float v = acc[i][j] * alpha;
            if (BIAS) v += bias[n];
            if (RELU) v = fmaxf(v, 0.f);
            if (RES)  v += res[(long)m * ldr + n];
            C[(long)m * ldc + n] = v;
        }
    }
}

// ---------------- launch ----------------
extern "C" void kernel_launch(void* const* d_in, const int* in_sizes, int n_in,
                              void* d_out, int out_size)
{
    const float* x     = (const float*)d_in[0];
    const float* wq    = (const float*)d_in[1];
    const float* wk    = (const float*)d_in[2];
    const float* wv    = (const float*)d_in[3];
    const float* w1    = (const float*)d_in[4];
    const float* b1    = (const float*)d_in[5];
    const float* w2    = (const float*)d_in[6];
    const float* b2    = (const float*)d_in[7];
    const float* ln1_g = (const float*)d_in[8];
    const float* ln1_b = (const float*)d_in[9];
    const float* ln2_g = (const float*)d_in[10];
    const float* ln2_b = (const float*)d_in[11];
    float* out = (float*)d_out;

    float *h, *q, *k, *v, *sc, *xmid, *ff1;
    cudaGetSymbolAddress((void**)&h,    g_h);
    cudaGetSymbolAddress((void**)&q,    g_q);
    cudaGetSymbolAddress((void**)&k,    g_k);
    cudaGetSymbolAddress((void**)&v,    g_v);
    cudaGetSymbolAddress((void**)&sc,   g_scores);
    cudaGetSymbolAddress((void**)&xmid, g_xmid);
    cudaGetSymbolAddress((void**)&ff1,  g_ff1);

    const float scale = 11.3137084989847604f;  // sqrt(128)
    const long TC   = (long)T_ * C_;           // 2048*1024
    const long HTD  = (long)T_ * DH_;          // 262144 (per-head q/k/v batch)
    const long BTD  = (long)H_ * HTD;          // 2097152 (per-b q/k/v batch)
    const long STT  = (long)T_ * T_;           // per-(b,h) scores
    const long SBB  = (long)H_ * STT;          // per-b scores

    // ---- LN1 ----
    ln_kernel<<<ROWS_, 256>>>(x, ln1_g, ln1_b, h);

    // ---- QKV: per (b,h): [2048x1024] @ [1024x128] -> q/k/v [B,H,T,Dh] ----
    dim3 gq(DH_/BN, T_/BM, B_*H_);
    gemm_kernel<false,false,false,false><<<gq, 256>>>(
        C_, h, C_, TC, 0,  wq, DH_, 0, (long)C_*DH_,
        q, DH_, BTD, HTD,  nullptr, nullptr, 0, 0, 0, 1.f, H_);
    gemm_kernel<false,false,false,false><<<gq, 256>>>(
        C_, h, C_, TC, 0,  wk, DH_, 0, (long)C_*DH_,
        k, DH_, BTD, HTD,  nullptr, nullptr, 0, 0, 0, 1.f, H_);
    gemm_kernel<false,false,false,false><<<gq, 256>>>(
        C_, h, C_, TC, 0,  wv, DH_, 0, (long)C_*DH_,
        v, DH_, BTD, HTD,  nullptr, nullptr, 0, 0, 0, 1.f, H_);

    // ---- scores = Q @ K^T * sqrt(Dh) ----
    dim3 gs(T_/BN, T_/BM, B_*H_);
    gemm_kernel<true,false,false,false><<<gs, 256>>>(
        DH_, q, DH_, BTD, HTD,  k, DH_, BTD, HTD,
        sc, T_, SBB, STT,  nullptr, nullptr, 0, 0, 0, scale, H_);

    // ---- softmax over s ----
    softmax_kernel<<<B_*H_*T_, 256>>>(sc);

    // ---- O = P @ V, write x + O into xmid ----
    dim3 go(DH_/BN, T_/BM, B_*H_);
    gemm_kernel<false,false,false,true><<<go, 256>>>(
        T_, sc, T_, SBB, STT,  v, DH_, BTD, HTD,
        xmid, C_, TC, DH_,  nullptr, x, C_, TC, DH_, 1.f, H_);

    // ---- LN2 ----
    ln_kernel<<<ROWS_, 256>>>(xmid, ln2_g, ln2_b, h);

    // ---- FF1: relu(h @ w1 + b1) ----
    dim3 g1(DFF_/BN, ROWS_/BM, 1);
    gemm_kernel<false,true,true,false><<<g1, 256>>>(
        C_, h, C_, 0, 0,  w1, DFF_, 0, 0,
        ff1, DFF_, 0, 0,  b1, nullptr, 0, 0, 0, 1.f, 1);

    // ---- FF2: out = xmid + ff1 @ w2 + b2 ----
    dim3 g2(C_/BN, ROWS_/BM, 1);
    gemm_kernel<false,false,true,true><<<g2, 256>>>(
        DFF_, ff1, DFF_, 0, 0,  w2, C_, 0, 0,
        out, C_, 0, 0,  b2, xmid, C_, 0, 0, 1.f, 1);
}

// round 4
// speedup vs baseline: 1.0446x; 1.0446x over previous
#include <cuda_runtime.h>
#include <math.h>

// ---------------- problem dims ----------------
#define B_  4
#define T_  2048
#define C_  1024
#define H_  8
#define DH_ 128
#define DFF_ 4096
#define ROWS_ (B_*T_)          // 8192

// ---------------- scratch (device globals; no allocs allowed) ----------------
__device__ float g_h[ROWS_*C_];
__device__ float g_q[ROWS_*C_];
__device__ float g_k[ROWS_*C_];
__device__ float g_v[ROWS_*C_];
__device__ float g_scores[(long)B_*H_*T_*T_];
__device__ float g_xmid[ROWS_*C_];
__device__ float g_ff1[ROWS_*DFF_];

// ---------------- LayerNorm ----------------
__global__ __launch_bounds__(256) void ln_kernel(
    const float* __restrict__ x, const float* __restrict__ g,
    const float* __restrict__ b, float* __restrict__ out)
{
    long row = blockIdx.x;
    const float* p = x + row * C_;
    int tid = threadIdx.x;
    float v[4];
    float s = 0.f, s2 = 0.f;
    #pragma unroll
    for (int i = 0; i < 4; i++) {
        v[i] = p[tid + i*256];
        s += v[i]; s2 += v[i]*v[i];
    }
    __shared__ float sh[2][8];
    #pragma unroll
    for (int o = 16; o; o >>= 1) {
        s  += __shfl_xor_sync(0xffffffffu, s,  o);
        s2 += __shfl_xor_sync(0xffffffffu, s2, o);
    }
    int lane = tid & 31, w = tid >> 5;
    if (lane == 0) { sh[0][w] = s; sh[1][w] = s2; }
    __syncthreads();
    if (tid == 0) {
        float a = 0.f, c = 0.f;
        #pragma unroll
        for (int i = 0; i < 8; i++) { a += sh[0][i]; c += sh[1][i]; }
        sh[0][0] = a; sh[1][0] = c;
    }
    __syncthreads();
    float mu  = sh[0][0] * (1.f / C_);
    float var = sh[1][0] * (1.f / C_) - mu * mu;
    float rstd = rsqrtf(var + 1e-5f);
    float* o = out + row * C_;
    #pragma unroll
    for (int i = 0; i < 4; i++) {
        int n = tid + i*256;
        o[n] = (v[i] - mu) * rstd * g[n] + b[n];
    }
}

// ---------------- Softmax over last dim (2048) ----------------
__global__ __launch_bounds__(256) void softmax_kernel(float* __restrict__ sc)
{
    long row = blockIdx.x;
    float* p = sc + row * (long)T_;
    int tid = threadIdx.x;
    float v[8];
    float m = -1e30f;
    #pragma unroll
    for (int i = 0; i < 8; i++) { v[i] = p[tid + i*256]; m = fmaxf(m, v[i]); }
    __shared__ float sh[8];
    __shared__ float res;
    int lane = tid & 31, w = tid >> 5;
    #pragma unroll
    for (int o = 16; o; o >>= 1) m = fmaxf(m, __shfl_xor_sync(0xffffffffu, m, o));
    if (lane == 0) sh[w] = m;
    __syncthreads();
    if (tid == 0) {
        float a = sh[0];
        #pragma unroll
        for (int i = 1; i < 8; i++) a = fmaxf(a, sh[i]);
        res = a;
    }
    __syncthreads();
    float mm = res;
    float sum = 0.f;
    #pragma unroll
    for (int i = 0; i < 8; i++) { v[i] = __expf(v[i] - mm); sum += v[i]; }
    __syncthreads();
    #pragma unroll
    for (int o = 16; o; o >>= 1) sum += __shfl_xor_sync(0xffffffffu, sum, o);
    if (lane == 0) sh[w] = sum;
    __syncthreads();
    if (tid == 0) {
        float a = 0.f;
        #pragma unroll
        for (int i = 0; i < 8; i++) a += sh[i];
        res = a;
    }
    __syncthreads();
    float inv = 1.f / res;
    #pragma unroll
    for (int i = 0; i < 8; i++) p[tid + i*256] = v[i] * inv;
}

// ---------------- 3xTF32 tensor-core batched GEMM ----------------
// C[m,n] = alpha * sum_k A[m,k]*B[k,n]  (TRB=false) or A[m,k]*B[n,k] (TRB=true)
// Error-compensated: each operand split into tf32 hi + lo; acc += hi*hi + hi*lo + lo*hi.
// 128x128 CTA tile, BK=16, 8 warps of 64x32, mma.m16n8k8.tf32, fp32 accumulate.
#define TBM 128
#define TBN 128
#define TBK 16
#define AS_LD 20     // As row stride (floats): conflict-free on fragment loads
#define BS_LD 136    // Bs row stride (floats): conflict-free on fragment loads

__device__ __forceinline__ unsigned f2tf(float f) {
    unsigned u;
    asm("cvt.rna.tf32.f32 %0, %1;" : "=r"(u) : "f"(f));
    return u;
}

__device__ __forceinline__ void mma_tf32(float* c, const unsigned* a, const unsigned* b) {
    asm volatile(
        "mma.sync.aligned.m16n8k8.row.col.f32.tf32.tf32.f32 "
        "{%0,%1,%2,%3}, {%4,%5,%6,%7}, {%8,%9}, {%0,%1,%2,%3};\n"
        : "+f"(c[0]), "+f"(c[1]), "+f"(c[2]), "+f"(c[3])
        : "r"(a[0]), "r"(a[1]), "r"(a[2]), "r"(a[3]), "r"(b[0]), "r"(b[1]));
}

template<bool TRB, bool RELU, bool BIAS, bool RES>
__global__ __launch_bounds__(256) void tgemm_kernel(
    int K,
    const float* __restrict__ A, int lda, long sAb, long sAh,
    const float* __restrict__ B, int ldb, long sBb, long sBh,
    float* __restrict__ C, int ldc, long sCb, long sCh,
    const float* __restrict__ bias,
    const float* __restrict__ res, int ldr, long sRb, long sRh,
    float alpha, int H)
{
    int z = blockIdx.z;
    int zb = z / H, zh = z - zb * H;
    A += zb * sAb + zh * sAh;
    B += zb * sBb + zh * sBh;
    C += zb * sCb + zh * sCh;
    if (RES) res += zb * sRb + zh * sRh;

    __shared__ float AsH[TBM * AS_LD];
    __shared__ float AsL[TBM * AS_LD];
    __shared__ float BsH[TBK * BS_LD];
    __shared__ float BsL[TBK * BS_LD];

    const int m0 = blockIdx.y * TBM;
    const int n0 = blockIdx.x * TBN;
    const int tid  = threadIdx.x;
    const int lane = tid & 31;
    const int warp = tid >> 5;
    const int g = lane >> 2;       // group 0..7
    const int t = lane & 3;        // 0..3
    const int mwarp = (warp >> 2) * 64;   // 0 or 64
    const int nwarp = (warp & 3) * 32;    // 0,32,64,96

    float acc[16][4];
    #pragma unroll
    for (int i = 0; i < 16; i++)
        #pragma unroll
        for (int j = 0; j < 4; j++) acc[i][j] = 0.f;

    const int am = tid >> 2;            // 0..63 (+64)
    const int ak = (tid & 3) * 4;       // 0,4,8,12
    const int bn = (tid & 31) * 4;
    const int bk = tid >> 5;            // (+8)
    const int tn = tid >> 2;            // TRB (+64)
    const int tk = (tid & 3) * 4;

    float4 ra0, ra1, rb0, rb1;

    auto load_tiles = [&](int k0) {
        ra0 = *(const float4*)&A[(long)(m0 + am)       * lda + k0 + ak];
        ra1 = *(const float4*)&A[(long)(m0 + am + 64)  * lda + k0 + ak];
        if (!TRB) {
            rb0 = *(const float4*)&B[(long)(k0 + bk)     * ldb + n0 + bn];
            rb1 = *(const float4*)&B[(long)(k0 + bk + 8) * ldb + n0 + bn];
        } else {
            rb0 = *(const float4*)&B[(long)(n0 + tn)      * ldb + k0 + tk];
            rb1 = *(const float4*)&B[(long)(n0 + tn + 64) * ldb + k0 + tk];
        }
    };

    auto split_store = [&](float v, float* hiArr, float* loArr, int idx) {
        unsigned h = f2tf(v);
        float hf = __uint_as_float(h);
        unsigned l = f2tf(v - hf);
        hiArr[idx] = hf;
        loArr[idx] = __uint_as_float(l);
    };

    auto store_tiles = [&]() {
        float va0[4] = {ra0.x, ra0.y, ra0.z, ra0.w};
        float va1[4] = {ra1.x, ra1.y, ra1.z, ra1.w};
        #pragma unroll
        for (int j = 0; j < 4; j++) {
            split_store(va0[j], AsH, AsL, am * AS_LD + ak + j);
            split_store(va1[j], AsH, AsL, (am + 64) * AS_LD + ak + j);
        }
        float vb0[4] = {rb0.x, rb0.y, rb0.z, rb0.w};
        float vb1[4] = {rb1.x, rb1.y, rb1.z, rb1.w};
        if (!TRB) {
            #pragma unroll
            for (int j = 0; j < 4; j++) {
                split_store(vb0[j], BsH, BsL, bk * BS_LD + bn + j);
                split_store(vb1[j], BsH, BsL, (bk + 8) * BS_LD + bn + j);
            }
        } else {
            #pragma unroll
            for (int j = 0; j < 4; j++) {
                split_store(vb0[j], BsH, BsL, (tk + j) * BS_LD + tn);
                split_store(vb1[j], BsH, BsL, (tk + j) * BS_LD + tn + 64);
            }
        }
    };

    load_tiles(0);
    for (int k0 = 0; k0 < K; k0 += TBK) {
        store_tiles();
        __syncthreads();
        if (k0 + TBK < K) load_tiles(k0 + TBK);

        #pragma unroll
        for (int ks = 0; ks < 2; ks++) {
            const int kk = ks * 8;
            unsigned bfh[4][2], bfl[4][2];
            #pragma unroll
            for (int nt = 0; nt < 4; nt++) {
                int cn = nwarp + nt * 8 + g;
                bfh[nt][0] = __float_as_uint(BsH[(kk + t) * BS_LD + cn]);
                bfh[nt][1] = __float_as_uint(BsH[(kk + t + 4) * BS_LD + cn]);
                bfl[nt][0] = __float_as_uint(BsL[(kk + t) * BS_LD + cn]);
                bfl[nt][1] = __float_as_uint(BsL[(kk + t + 4) * BS_LD + cn]);
            }
            #pragma unroll
            for (int mt = 0; mt < 4; mt++) {
                int r0 = mwarp + mt * 16 + g;
                unsigned afh[4], afl[4];
                afh[0] = __float_as_uint(AsH[r0 * AS_LD + kk + t]);
                afh[1] = __float_as_uint(AsH[(r0 + 8) * AS_LD + kk + t]);
                afh[2] = __float_as_uint(AsH[r0 * AS_LD + kk + t + 4]);
                afh[3] = __float_as_uint(AsH[(r0 + 8) * AS_LD + kk + t + 4]);
                afl[0] = __float_as_uint(AsL[r0 * AS_LD + kk + t]);
                afl[1] = __float_as_uint(AsL[(r0 + 8) * AS_LD + kk + t]);
                afl[2] = __float_as_uint(AsL[r0 * AS_LD + kk + t + 4]);
                afl[3] = __float_as_uint(AsL[(r0 + 8) * AS_LD + kk + t + 4]);
                #pragma unroll
                for (int nt = 0; nt < 4; nt++) {
                    mma_tf32(acc[mt * 4 + nt], afh, bfh[nt]);  // hi*hi
                    mma_tf32(acc[mt * 4 + nt], afl, bfh[nt]);  // lo*hi
                    mma_tf32(acc[mt * 4 + nt], afh, bfl[nt]);  // hi*lo
                }
            }
        }
        __syncthreads();
    }

    // ---- epilogue ----
    #pragma unroll
    for (int mt = 0; mt < 4; mt++) {
        #pragma unroll
        for (int nt = 0; nt < 4; nt++) {
            const float* a4 = acc[mt * 4 + nt];
            int rr = m0 + mwarp + mt * 16 + g;
            int cc = n0 + nwarp + nt * 8 + 2 * t;
            #pragma unroll
            for (int half = 0; half < 2; half++) {
                int m = rr + half * 8;
                float v0 = a4[half * 2 + 0] * alpha;
                float v1 = a4[half * 2 + 1] * alpha;
                if (BIAS) { v0 += bias[cc]; v1 += bias[cc + 1]; }
                if (RELU) { v0 = fmaxf(v0, 0.f); v1 = fmaxf(v1, 0.f); }
                if (RES) {
                    v0 += res[(long)m * ldr + cc];
                    v1 += res[(long)m * ldr + cc + 1];
                }
                C[(long)m * ldc + cc]     = v0;
                C[(long)m * ldc + cc + 1] = v1;
            }
        }
    }
}

// ---------------- launch ----------------
extern "C" void kernel_launch(void* const* d_in, const int* in_sizes, int n_in,
                              void* d_out, int out_size)
{
    const float* x     = (const float*)d_in[0];
    const float* wq    = (const float*)d_in[1];
    const float* wk    = (const float*)d_in[2];
    const float* wv    = (const float*)d_in[3];
    const float* w1    = (const float*)d_in[4];
    const float* b1    = (const float*)d_in[5];
    const float* w2    = (const float*)d_in[6];
    const float* b2    = (const float*)d_in[7];
    const float* ln1_g = (const float*)d_in[8];
    const float* ln1_b = (const float*)d_in[9];
    const float* ln2_g = (const float*)d_in[10];
    const float* ln2_b = (const float*)d_in[11];
    float* out = (float*)d_out;

    float *h, *q, *k, *v, *sc, *xmid, *ff1;
    cudaGetSymbolAddress((void**)&h,    g_h);
    cudaGetSymbolAddress((void**)&q,    g_q);
    cudaGetSymbolAddress((void**)&k,    g_k);
    cudaGetSymbolAddress((void**)&v,    g_v);
    cudaGetSymbolAddress((void**)&sc,   g_scores);
    cudaGetSymbolAddress((void**)&xmid, g_xmid);
    cudaGetSymbolAddress((void**)&ff1,  g_ff1);

    const float scale = 11.3137084989847604f;  // sqrt(128)
    const long TC   = (long)T_ * C_;
    const long HTD  = (long)T_ * DH_;
    const long BTD  = (long)H_ * HTD;
    const long STT  = (long)T_ * T_;
    const long SBB  = (long)H_ * STT;

    // ---- LN1 ----
    ln_kernel<<<ROWS_, 256>>>(x, ln1_g, ln1_b, h);

    // ---- QKV ----
    dim3 gq(DH_/TBN, T_/TBM, B_*H_);
    tgemm_kernel<false,false,false,false><<<gq, 256>>>(
        C_, h, C_, TC, 0,  wq, DH_, 0, (long)C_*DH_,
        q, DH_, BTD, HTD,  nullptr, nullptr, 0, 0, 0, 1.f, H_);
    tgemm_kernel<false,false,false,false><<<gq, 256>>>(
        C_, h, C_, TC, 0,  wk, DH_, 0, (long)C_*DH_,
        k, DH_, BTD, HTD,  nullptr, nullptr, 0, 0, 0, 1.f, H_);
    tgemm_kernel<false,false,false,false><<<gq, 256>>>(
        C_, h, C_, TC, 0,  wv, DH_, 0, (long)C_*DH_,
        v, DH_, BTD, HTD,  nullptr, nullptr, 0, 0, 0, 1.f, H_);

    // ---- scores = Q @ K^T * sqrt(Dh) ----
    dim3 gs(T_/TBN, T_/TBM, B_*H_);
    tgemm_kernel<true,false,false,false><<<gs, 256>>>(
        DH_, q, DH_, BTD, HTD,  k, DH_, BTD, HTD,
        sc, T_, SBB, STT,  nullptr, nullptr, 0, 0, 0, scale, H_);

    // ---- softmax ----
    softmax_kernel<<<B_*H_*T_, 256>>>(sc);

    // ---- O = P @ V, + residual x -> xmid ----
    dim3 go(DH_/TBN, T_/TBM, B_*H_);
    tgemm_kernel<false,false,false,true><<<go, 256>>>(
        T_, sc, T_, SBB, STT,  v, DH_, BTD, HTD,
        xmid, C_, TC, DH_,  nullptr, x, C_, TC, DH_, 1.f, H_);

    // ---- LN2 ----
    ln_kernel<<<ROWS_, 256>>>(xmid, ln2_g, ln2_b, h);

    // ---- FF1 ----
    dim3 g1(DFF_/TBN, ROWS_/TBM, 1);
    tgemm_kernel<false,true,true,false><<<g1, 256>>>(
        C_, h, C_, 0, 0,  w1, DFF_, 0, 0,
        ff1, DFF_, 0, 0,  b1, nullptr, 0, 0, 0, 1.f, 1);

    // ---- FF2 ----
    dim3 g2(C_/TBN, ROWS_/TBM, 1);
    tgemm_kernel<false,false,true,true><<<g2, 256>>>(
        DFF_, ff1, DFF_, 0, 0,  w2, C_, 0, 0,
        out, C_, 0, 0,  b2, xmid, C_, 0, 0, 1.f, 1);
}

// round 6
// speedup vs baseline: 1.7391x; 1.6648x over previous
#include <cuda_runtime.h>
#include <math.h>

// ---------------- problem dims ----------------
#define B_  4
#define T_  2048
#define C_  1024
#define H_  8
#define DH_ 128
#define DFF_ 4096
#define ROWS_ (B_*T_)          // 8192

// ---------------- scratch (device globals; no allocs allowed) ----------------
__device__ float g_h[ROWS_*C_];
__device__ float g_q[ROWS_*C_];
__device__ float g_k[ROWS_*C_];
__device__ float g_v[ROWS_*C_];
__device__ float g_scores[(long)B_*H_*T_*T_];
__device__ float g_xmid[ROWS_*C_];
__device__ float g_ff1[ROWS_*DFF_];

// ---------------- LayerNorm ----------------
__global__ __launch_bounds__(256) void ln_kernel(
    const float* __restrict__ x, const float* __restrict__ g,
    const float* __restrict__ b, float* __restrict__ out)
{
    long row = blockIdx.x;
    const float* p = x + row * C_;
    int tid = threadIdx.x;
    float v[4];
    float s = 0.f, s2 = 0.f;
    #pragma unroll
    for (int i = 0; i < 4; i++) {
        v[i] = p[tid + i*256];
        s += v[i]; s2 += v[i]*v[i];
    }
    __shared__ float sh[2][8];
    #pragma unroll
    for (int o = 16; o; o >>= 1) {
        s  += __shfl_xor_sync(0xffffffffu, s,  o);
        s2 += __shfl_xor_sync(0xffffffffu, s2, o);
    }
    int lane = tid & 31, w = tid >> 5;
    if (lane == 0) { sh[0][w] = s; sh[1][w] = s2; }
    __syncthreads();
    if (tid == 0) {
        float a = 0.f, c = 0.f;
        #pragma unroll
        for (int i = 0; i < 8; i++) { a += sh[0][i]; c += sh[1][i]; }
        sh[0][0] = a; sh[1][0] = c;
    }
    __syncthreads();
    float mu  = sh[0][0] * (1.f / C_);
    float var = sh[1][0] * (1.f / C_) - mu * mu;
    float rstd = rsqrtf(var + 1e-5f);
    float* o = out + row * C_;
    #pragma unroll
    for (int i = 0; i < 4; i++) {
        int n = tid + i*256;
        o[n] = (v[i] - mu) * rstd * g[n] + b[n];
    }
}

// ---------------- Softmax over last dim (2048) ----------------
__global__ __launch_bounds__(256) void softmax_kernel(float* __restrict__ sc)
{
    long row = blockIdx.x;
    float* p = sc + row * (long)T_;
    int tid = threadIdx.x;
    float v[8];
    float m = -1e30f;
    #pragma unroll
    for (int i = 0; i < 8; i++) { v[i] = p[tid + i*256]; m = fmaxf(m, v[i]); }
    __shared__ float sh[8];
    __shared__ float res;
    int lane = tid & 31, w = tid >> 5;
    #pragma unroll
    for (int o = 16; o; o >>= 1) m = fmaxf(m, __shfl_xor_sync(0xffffffffu, m, o));
    if (lane == 0) sh[w] = m;
    __syncthreads();
    if (tid == 0) {
        float a = sh[0];
        #pragma unroll
        for (int i = 1; i < 8; i++) a = fmaxf(a, sh[i]);
        res = a;
    }
    __syncthreads();
    float mm = res;
    float sum = 0.f;
    #pragma unroll
    for (int i = 0; i < 8; i++) { v[i] = __expf(v[i] - mm); sum += v[i]; }
    __syncthreads();
    #pragma unroll
    for (int o = 16; o; o >>= 1) sum += __shfl_xor_sync(0xffffffffu, sum, o);
    if (lane == 0) sh[w] = sum;
    __syncthreads();
    if (tid == 0) {
        float a = 0.f;
        #pragma unroll
        for (int i = 0; i < 8; i++) a += sh[i];
        res = a;
    }
    __syncthreads();
    float inv = 1.f / res;
    #pragma unroll
    for (int i = 0; i < 8; i++) p[tid + i*256] = v[i] * inv;
}

// ---------------- 3xTF32 tensor-core batched GEMM (cp.async, dbl-buffered) ----
// C[m,n] = alpha * sum_k A[m,k]*B[k,n]  (TRB=false) or A[m,k]*B[n,k] (TRB=true)
// Raw fp32 tiles in smem; tf32 hi/lo bitmask split at fragment-load time.
// 128x128 CTA tile, BK=16, 8 warps of 64x32, term-major MMA issue.
#define TBM 128
#define TBN 128
#define TBK 16
#define AS_LD 20     // [row][k] stride: (20g+t)%32 bijective -> conflict-free frags
#define BS_LD 136    // [k][n] stride:   (8t+g)%32  bijective -> conflict-free frags

__device__ __forceinline__ void split2(float v, unsigned& hi, unsigned& lo) {
    unsigned u = __float_as_uint(v) & 0xffffe000u;
    hi = u;
    float l = v - __uint_as_float(u);
    lo = __float_as_uint(l) & 0xffffe000u;
}

__device__ __forceinline__ void mma_tf32(float* c, const unsigned* a, const unsigned* b) {
    asm("mma.sync.aligned.m16n8k8.row.col.f32.tf32.tf32.f32 "
        "{%0,%1,%2,%3}, {%4,%5,%6,%7}, {%8,%9}, {%0,%1,%2,%3};\n"
        : "+f"(c[0]), "+f"(c[1]), "+f"(c[2]), "+f"(c[3])
        : "r"(a[0]), "r"(a[1]), "r"(a[2]), "r"(a[3]), "r"(b[0]), "r"(b[1]));
}

__device__ __forceinline__ void cp16(float* smem_dst, const float* gmem_src) {
    unsigned s = (unsigned)__cvta_generic_to_shared(smem_dst);
    asm volatile("cp.async.cg.shared.global [%0], [%1], 16;\n" :: "r"(s), "l"(gmem_src));
}

template<bool TRB, bool RELU, bool BIAS, bool RES>
__global__ __launch_bounds__(256, 2) void tgemm_kernel(
    int K,
    const float* __restrict__ A, int lda, long sAb, long sAh,
    const float* __restrict__ B, int ldb, long sBb, long sBh,
    float* __restrict__ C, int ldc, long sCb, long sCh,
    const float* __restrict__ bias,
    const float* __restrict__ res, int ldr, long sRb, long sRh,
    float alpha, int H)
{
    int z = blockIdx.z;
    int zb = z / H, zh = z - zb * H;
    A += zb * sAb + zh * sAh;
    B += zb * sBb + zh * sBh;
    C += zb * sCb + zh * sCh;
    if (RES) res += zb * sRb + zh * sRh;

    constexpr int ASZ = TBM * AS_LD;                     // 2560 floats
    constexpr int BSZ = TRB ? (TBN * AS_LD) : (TBK * BS_LD);
    __shared__ float As[2 * ASZ];
    __shared__ float Bs[2 * BSZ];

    const int m0 = blockIdx.y * TBM;
    const int n0 = blockIdx.x * TBN;
    const int tid  = threadIdx.x;
    const int lane = tid & 31;
    const int warp = tid >> 5;
    const int g = lane >> 2;              // 0..7
    const int t = lane & 3;               // 0..3
    const int mwarp = (warp >> 2) * 64;   // 0 or 64
    const int nwarp = (warp & 3) * 32;    // 0,32,64,96

    float acc[16][4];
    #pragma unroll
    for (int i = 0; i < 16; i++)
        #pragma unroll
        for (int j = 0; j < 4; j++) acc[i][j] = 0.f;

    const int am = tid >> 2;              // 0..63 (+64)
    const int ak = (tid & 3) * 4;         // 0,4,8,12
    const int bn = (tid & 31) * 4;        // !TRB
    const int bk = tid >> 5;              // !TRB (+8)
    const int tn = tid >> 2;              // TRB (+64)
    const int tk = (tid & 3) * 4;         // TRB

    auto issue_loads = [&](int k0, int buf) {
        float* Ad = As + buf * ASZ;
        cp16(&Ad[am * AS_LD + ak],        &A[(long)(m0 + am)      * lda + k0 + ak]);
        cp16(&Ad[(am + 64) * AS_LD + ak], &A[(long)(m0 + am + 64) * lda + k0 + ak]);
        float* Bd = Bs + buf * BSZ;
        if (!TRB) {
            cp16(&Bd[bk * BS_LD + bn],       &B[(long)(k0 + bk)     * ldb + n0 + bn]);
            cp16(&Bd[(bk + 8) * BS_LD + bn], &B[(long)(k0 + bk + 8) * ldb + n0 + bn]);
        } else {
            cp16(&Bd[tn * AS_LD + tk],        &B[(long)(n0 + tn)      * ldb + k0 + tk]);
            cp16(&Bd[(tn + 64) * AS_LD + tk], &B[(long)(n0 + tn + 64) * ldb + k0 + tk]);
        }
        asm volatile("cp.async.commit_group;\n");
    };

    issue_loads(0, 0);
    const int nIter = K / TBK;

    for (int i = 0; i < nIter; i++) {
        asm volatile("cp.async.wait_group 0;\n");
        __syncthreads();
        if (i + 1 < nIter) issue_loads((i + 1) * TBK, (i + 1) & 1);

        const float* Ab = As + (i & 1) * ASZ;
        const float* Bb = Bs + (i & 1) * BSZ;

        #pragma unroll
        for (int ks = 0; ks < 2; ks++) {
            const int kk = ks * 8;
            unsigned afh[4][4], afl[4][4], bfh[4][2], bfl[4][2];
            #pragma unroll
            for (int mt = 0; mt < 4; mt++) {
                int r0 = mwarp + mt * 16 + g;
                split2(Ab[r0 * AS_LD + kk + t],           afh[mt][0], afl[mt][0]);
                split2(Ab[(r0 + 8) * AS_LD + kk + t],     afh[mt][1], afl[mt][1]);
                split2(Ab[r0 * AS_LD + kk + t + 4],       afh[mt][2], afl[mt][2]);
                split2(Ab[(r0 + 8) * AS_LD + kk + t + 4], afh[mt][3], afl[mt][3]);
            }
            #pragma unroll
            for (int nt = 0; nt < 4; nt++) {
                int cn = nwarp + nt * 8 + g;
                float b0, b1;
                if (!TRB) {
                    b0 = Bb[(kk + t) * BS_LD + cn];
                    b1 = Bb[(kk + t + 4) * BS_LD + cn];
                } else {
                    b0 = Bb[cn * AS_LD + kk + t];
                    b1 = Bb[cn * AS_LD + kk + t + 4];
                }
                split2(b0, bfh[nt][0], bfl[nt][0]);
                split2(b1, bfh[nt][1], bfl[nt][1]);
            }
            // term-major: 16 independent MMAs between accumulator reuses
            #pragma unroll
            for (int mt = 0; mt < 4; mt++)
                #pragma unroll
                for (int nt = 0; nt < 4; nt++)
                    mma_tf32(acc[mt * 4 + nt], afh[mt], bfh[nt]);   // hi*hi
            #pragma unroll
            for (int mt = 0; mt < 4; mt++)
                #pragma unroll
                for (int nt = 0; nt < 4; nt++)
                    mma_tf32(acc[mt * 4 + nt], afl[mt], bfh[nt]);   // lo*hi
            #pragma unroll
            for (int mt = 0; mt < 4; mt++)
                #pragma unroll
                for (int nt = 0; nt < 4; nt++)
                    mma_tf32(acc[mt * 4 + nt], afh[mt], bfl[nt]);   // hi*lo
        }
        __syncthreads();
    }

    // ---- epilogue ----
    #pragma unroll
    for (int mt = 0; mt < 4; mt++) {
        #pragma unroll
        for (int nt = 0; nt < 4; nt++) {
            const float* a4 = acc[mt * 4 + nt];
            int rr = m0 + mwarp + mt * 16 + g;
            int cc = n0 + nwarp + nt * 8 + 2 * t;
            #pragma unroll
            for (int half = 0; half < 2; half++) {
                int m = rr + half * 8;
                float v0 = a4[half * 2 + 0] * alpha;
                float v1 = a4[half * 2 + 1] * alpha;
                if (BIAS) { v0 += bias[cc]; v1 += bias[cc + 1]; }
                if (RELU) { v0 = fmaxf(v0, 0.f); v1 = fmaxf(v1, 0.f); }
                if (RES) {
                    v0 += res[(long)m * ldr + cc];
                    v1 += res[(long)m * ldr + cc + 1];
                }
                C[(long)m * ldc + cc]     = v0;
                C[(long)m * ldc + cc + 1] = v1;
            }
        }
    }
}

// ---------------- launch ----------------
extern "C" void kernel_launch(void* const* d_in, const int* in_sizes, int n_in,
                              void* d_out, int out_size)
{
    const float* x     = (const float*)d_in[0];
    const float* wq    = (const float*)d_in[1];
    const float* wk    = (const float*)d_in[2];
    const float* wv    = (const float*)d_in[3];
    const float* w1    = (const float*)d_in[4];
    const float* b1    = (const float*)d_in[5];
    const float* w2    = (const float*)d_in[6];
    const float* b2    = (const float*)d_in[7];
    const float* ln1_g = (const float*)d_in[8];
    const float* ln1_b = (const float*)d_in[9];
    const float* ln2_g = (const float*)d_in[10];
    const float* ln2_b = (const float*)d_in[11];
    float* out = (float*)d_out;

    float *h, *q, *k, *v, *sc, *xmid, *ff1;
    cudaGetSymbolAddress((void**)&h,    g_h);
    cudaGetSymbolAddress((void**)&q,    g_q);
    cudaGetSymbolAddress((void**)&k,    g_k);
    cudaGetSymbolAddress((void**)&v,    g_v);
    cudaGetSymbolAddress((void**)&sc,   g_scores);
    cudaGetSymbolAddress((void**)&xmid, g_xmid);
    cudaGetSymbolAddress((void**)&ff1,  g_ff1);

    const float scale = 11.3137084989847604f;  // sqrt(128)
    const long TC   = (long)T_ * C_;
    const long HTD  = (long)T_ * DH_;
    const long BTD  = (long)H_ * HTD;
    const long STT  = (long)T_ * T_;
    const long SBB  = (long)H_ * STT;

    // ---- LN1 ----
    ln_kernel<<<ROWS_, 256>>>(x, ln1_g, ln1_b, h);

    // ---- QKV ----
    dim3 gq(DH_/TBN, T_/TBM, B_*H_);
    tgemm_kernel<false,false,false,false><<<gq, 256>>>(
        C_, h, C_, TC, 0,  wq, DH_, 0, (long)C_*DH_,
        q, DH_, BTD, HTD,  nullptr, nullptr, 0, 0, 0, 1.f, H_);
    tgemm_kernel<false,false,false,false><<<gq, 256>>>(
        C_, h, C_, TC, 0,  wk, DH_, 0, (long)C_*DH_,
        k, DH_, BTD, HTD,  nullptr, nullptr, 0, 0, 0, 1.f, H_);
    tgemm_kernel<false,false,false,false><<<gq, 256>>>(
        C_, h, C_, TC, 0,  wv, DH_, 0, (long)C_*DH_,
        v, DH_, BTD, HTD,  nullptr, nullptr, 0, 0, 0, 1.f, H_);

    // ---- scores = Q @ K^T * sqrt(Dh) ----
    dim3 gs(T_/TBN, T_/TBM, B_*H_);
    tgemm_kernel<true,false,false,false><<<gs, 256>>>(
        DH_, q, DH_, BTD, HTD,  k, DH_, BTD, HTD,
        sc, T_, SBB, STT,  nullptr, nullptr, 0, 0, 0, scale, H_);

    // ---- softmax ----
    softmax_kernel<<<B_*H_*T_, 256>>>(sc);

    // ---- O = P @ V, + residual x -> xmid ----
    dim3 go(DH_/TBN, T_/TBM, B_*H_);
    tgemm_kernel<false,false,false,true><<<go, 256>>>(
        T_, sc, T_, SBB, STT,  v, DH_, BTD, HTD,
        xmid, C_, TC, DH_,  nullptr, x, C_, TC, DH_, 1.f, H_);

    // ---- LN2 ----
    ln_kernel<<<ROWS_, 256>>>(xmid, ln2_g, ln2_b, h);

    // ---- FF1 ----
    dim3 g1(DFF_/TBN, ROWS_/TBM, 1);
    tgemm_kernel<false,true,true,false><<<g1, 256>>>(
        C_, h, C_, 0, 0,  w1, DFF_, 0, 0,
        ff1, DFF_, 0, 0,  b1, nullptr, 0, 0, 0, 1.f, 1);

    // ---- FF2 ----
    dim3 g2(C_/TBN, ROWS_/TBM, 1);
    tgemm_kernel<false,false,true,true><<<g2, 256>>>(
        DFF_, ff1, DFF_, 0, 0,  w2, C_, 0, 0,
        out, C_, 0, 0,  b2, xmid, C_, 0, 0, 1.f, 1);
}

// round 7
// speedup vs baseline: 2.0546x; 1.1814x over previous
#include <cuda_runtime.h>
#include <cuda_fp16.h>
#include <math.h>

// ---------------- problem dims ----------------
#define B_  4
#define T_  2048
#define C_  1024
#define H_  8
#define DH_ 128
#define DFF_ 4096
#define ROWS_ (B_*T_)          // 8192

typedef unsigned int u32;

// ---------------- scratch (device globals; no allocs allowed) ----------------
__device__ __align__(16) __half g_hH[ROWS_*C_],  g_hL[ROWS_*C_];      // LN out
__device__ __align__(16) __half g_wqTH[H_*DH_*C_], g_wqTL[H_*DH_*C_];
__device__ __align__(16) __half g_wkTH[H_*DH_*C_], g_wkTL[H_*DH_*C_];
__device__ __align__(16) __half g_wvTH[H_*DH_*C_], g_wvTL[H_*DH_*C_];
__device__ __align__(16) __half g_w1TH[C_*DFF_],   g_w1TL[C_*DFF_];   // [Dff][C]
__device__ __align__(16) __half g_w2TH[C_*DFF_],   g_w2TL[C_*DFF_];   // [C][Dff]
__device__ __align__(16) __half g_qH[ROWS_*C_],  g_qL[ROWS_*C_];      // [B,H,T,Dh]
__device__ __align__(16) __half g_kH[ROWS_*C_],  g_kL[ROWS_*C_];
__device__ __align__(16) __half g_vH[ROWS_*C_],  g_vL[ROWS_*C_];
__device__ __align__(16) __half g_vtH[ROWS_*C_], g_vtL[ROWS_*C_];     // [B,H,Dh,T]
__device__ float g_scores[(long)B_*H_*T_*T_];                          // fp32
__device__ __align__(16) __half g_pH[(long)B_*H_*T_*T_], g_pL[(long)B_*H_*T_*T_];
__device__ __align__(16) __half g_ff1H[(long)ROWS_*DFF_], g_ff1L[(long)ROWS_*DFF_];
__device__ float g_xmid[ROWS_*C_];

// ---------------- helpers ----------------
__device__ __forceinline__ void fsplit(float v, __half& hi, __half& lo) {
    hi = __float2half_rn(v);
    lo = __float2half_rn(v - __half2float(hi));
}

// ---------------- LayerNorm -> fp16 hi/lo ----------------
__global__ __launch_bounds__(256) void ln_split_kernel(
    const float* __restrict__ x, const float* __restrict__ g,
    const float* __restrict__ b, __half* __restrict__ oh, __half* __restrict__ ol)
{
    long row = blockIdx.x;
    const float* p = x + row * C_;
    int tid = threadIdx.x;
    float v[4];
    float s = 0.f, s2 = 0.f;
    #pragma unroll
    for (int i = 0; i < 4; i++) {
        v[i] = p[tid + i*256];
        s += v[i]; s2 += v[i]*v[i];
    }
    __shared__ float sh[2][8];
    #pragma unroll
    for (int o = 16; o; o >>= 1) {
        s  += __shfl_xor_sync(0xffffffffu, s,  o);
        s2 += __shfl_xor_sync(0xffffffffu, s2, o);
    }
    int lane = tid & 31, w = tid >> 5;
    if (lane == 0) { sh[0][w] = s; sh[1][w] = s2; }
    __syncthreads();
    if (tid == 0) {
        float a = 0.f, c = 0.f;
        #pragma unroll
        for (int i = 0; i < 8; i++) { a += sh[0][i]; c += sh[1][i]; }
        sh[0][0] = a; sh[1][0] = c;
    }
    __syncthreads();
    float mu  = sh[0][0] * (1.f / C_);
    float var = sh[1][0] * (1.f / C_) - mu * mu;
    float rstd = rsqrtf(var + 1e-5f);
    #pragma unroll
    for (int i = 0; i < 4; i++) {
        int n = tid + i*256;
        float o = (v[i] - mu) * rstd * g[n] + b[n];
        __half hi, lo; fsplit(o, hi, lo);
        oh[row * C_ + n] = hi;
        ol[row * C_ + n] = lo;
    }
}

// ---------------- Softmax -> fp16 hi/lo probs ----------------
__global__ __launch_bounds__(256) void softmax_split_kernel(
    const float* __restrict__ sc, __half* __restrict__ ph, __half* __restrict__ pl)
{
    long row = blockIdx.x;
    const float* p = sc + row * (long)T_;
    int tid = threadIdx.x;
    float v[8];
    float m = -1e30f;
    #pragma unroll
    for (int i = 0; i < 8; i++) { v[i] = p[tid + i*256]; m = fmaxf(m, v[i]); }
    __shared__ float sh[8];
    __shared__ float res;
    int lane = tid & 31, w = tid >> 5;
    #pragma unroll
    for (int o = 16; o; o >>= 1) m = fmaxf(m, __shfl_xor_sync(0xffffffffu, m, o));
    if (lane == 0) sh[w] = m;
    __syncthreads();
    if (tid == 0) {
        float a = sh[0];
        #pragma unroll
        for (int i = 1; i < 8; i++) a = fmaxf(a, sh[i]);
        res = a;
    }
    __syncthreads();
    float mm = res;
    float sum = 0.f;
    #pragma unroll
    for (int i = 0; i < 8; i++) { v[i] = __expf(v[i] - mm); sum += v[i]; }
    __syncthreads();
    #pragma unroll
    for (int o = 16; o; o >>= 1) sum += __shfl_xor_sync(0xffffffffu, sum, o);
    if (lane == 0) sh[w] = sum;
    __syncthreads();
    if (tid == 0) {
        float a = 0.f;
        #pragma unroll
        for (int i = 0; i < 8; i++) a += sh[i];
        res = a;
    }
    __syncthreads();
    float inv = 1.f / res;
    #pragma unroll
    for (int i = 0; i < 8; i++) {
        float pv = v[i] * inv;
        __half hi, lo; fsplit(pv, hi, lo);
        ph[row * (long)T_ + tid + i*256] = hi;
        pl[row * (long)T_ + tid + i*256] = lo;
    }
}

// ---------------- transpose fp32 -> split fp16 hi/lo ----------------
// in [z][R][Cc] fp32  ->  out [z][Cc][R] fp16 hi/lo
__global__ __launch_bounds__(256) void tr_split32_kernel(
    const float* __restrict__ in, __half* __restrict__ oh, __half* __restrict__ ol,
    int R, int Cc)
{
    long zo = (long)blockIdx.z * R * Cc;
    in += zo; oh += zo; ol += zo;
    __shared__ float t[32][33];
    int c0 = blockIdx.x * 32, r0 = blockIdx.y * 32;
    int tid = threadIdx.x;
    int tx = tid & 31, ty = tid >> 5;
    #pragma unroll
    for (int j = 0; j < 4; j++)
        t[ty + j*8][tx] = in[(long)(r0 + ty + j*8) * Cc + c0 + tx];
    __syncthreads();
    #pragma unroll
    for (int j = 0; j < 4; j++) {
        float v = t[tx][ty + j*8];
        __half hi, lo; fsplit(v, hi, lo);
        long idx = (long)(c0 + ty + j*8) * R + r0 + tx;
        oh[idx] = hi; ol[idx] = lo;
    }
}

// ---------------- transpose fp16 pair ----------------
// in hi/lo [z][R][Cc] -> out hi/lo [z][Cc][R]
__global__ __launch_bounds__(256) void tr_pair16_kernel(
    const __half* __restrict__ ih, const __half* __restrict__ il,
    __half* __restrict__ oh, __half* __restrict__ ol, int R, int Cc)
{
    long zo = (long)blockIdx.z * R * Cc;
    ih += zo; il += zo; oh += zo; ol += zo;
    __shared__ __half th[32][34];
    __shared__ __half tl[32][34];
    int c0 = blockIdx.x * 32, r0 = blockIdx.y * 32;
    int tid = threadIdx.x;
    int tx = tid & 31, ty = tid >> 5;
    #pragma unroll
    for (int j = 0; j < 4; j++) {
        long idx = (long)(r0 + ty + j*8) * Cc + c0 + tx;
        th[ty + j*8][tx] = ih[idx];
        tl[ty + j*8][tx] = il[idx];
    }
    __syncthreads();
    #pragma unroll
    for (int j = 0; j < 4; j++) {
        long idx = (long)(c0 + ty + j*8) * R + r0 + tx;
        oh[idx] = th[tx][ty + j*8];
        ol[idx] = tl[tx][ty + j*8];
    }
}

// ---------------- 3xFP16 tensor-core batched GEMM ----------------
// C[m,n] = alpha * sum_k A[m,k] * Bt[n,k]   (both operands K-major, hi/lo fp16)
// 128x128 CTA tile, BK=16, 8 warps of 64x32, m16n8k16, fp32 accumulate.
#define SLD 24                    // halves per smem row (48B, 16B-aligned, LDSM-conflict-free)
#define TILEH (128*SLD)           // halves per tile

__device__ __forceinline__ void ldsm4(u32 addr, u32& r0, u32& r1, u32& r2, u32& r3) {
    asm volatile("ldmatrix.sync.aligned.m8n8.x4.shared.b16 {%0,%1,%2,%3}, [%4];"
                 : "=r"(r0), "=r"(r1), "=r"(r2), "=r"(r3) : "r"(addr));
}

__device__ __forceinline__ void mma16(float* c, const u32* a, const u32* b) {
    asm("mma.sync.aligned.m16n8k16.row.col.f32.f16.f16.f32 "
        "{%0,%1,%2,%3}, {%4,%5,%6,%7}, {%8,%9}, {%0,%1,%2,%3};\n"
        : "+f"(c[0]), "+f"(c[1]), "+f"(c[2]), "+f"(c[3])
        : "r"(a[0]), "r"(a[1]), "r"(a[2]), "r"(a[3]), "r"(b[0]), "r"(b[1]));
}

__device__ __forceinline__ void cp16h(__half* smem_dst, const __half* gmem_src) {
    u32 s = (u32)__cvta_generic_to_shared(smem_dst);
    asm volatile("cp.async.cg.shared.global [%0], [%1], 16;\n" :: "r"(s), "l"(gmem_src));
}

template<bool RELU, bool BIAS, bool RES, bool F16OUT>
__global__ __launch_bounds__(256, 2) void hgemm3_kernel(
    int K,
    const __half* __restrict__ Ahp, const __half* __restrict__ Alp, int lda, long sAb, long sAh,
    const __half* __restrict__ Bhp, const __half* __restrict__ Blp, int ldb, long sBb, long sBh,
    float* __restrict__ Cf, __half* __restrict__ Ch, __half* __restrict__ Cl,
    int ldc, long sCb, long sCh,
    const float* __restrict__ bias,
    const float* __restrict__ res, int ldr, long sRb, long sRh,
    float alpha, int H)
{
    int z = blockIdx.z;
    int zb = z / H, zh = z - zb * H;
    Ahp += zb * sAb + zh * sAh;  Alp += zb * sAb + zh * sAh;
    Bhp += zb * sBb + zh * sBh;  Blp += zb * sBb + zh * sBh;
    long co = zb * sCb + zh * sCh;
    if (F16OUT) { Ch += co; Cl += co; } else { Cf += co; }
    if (RES) res += zb * sRb + zh * sRh;

    // smem: [buf(2)][tile: AH, AL, BH, BL][128][SLD]
    __shared__ __align__(16) __half sm[2 * 4 * TILEH];

    const int m0 = blockIdx.y * 128;
    const int n0 = blockIdx.x * 128;
    const int tid  = threadIdx.x;
    const int lane = tid & 31;
    const int warp = tid >> 5;
    const int mwarp = (warp >> 2) * 64;   // 0 or 64
    const int nwarp = (warp & 3) * 32;    // 0,32,64,96
    const int g = lane >> 2;              // 0..7
    const int t = lane & 3;               // 0..3

    float acc[16][4];
    #pragma unroll
    for (int i = 0; i < 16; i++)
        #pragma unroll
        for (int j = 0; j < 4; j++) acc[i][j] = 0.f;

    const int ldrow = tid >> 1;           // 0..127
    const int ldseg = (tid & 1) * 8;      // 0 or 8 halves

    auto issue_loads = [&](int k0, int buf) {
        __half* base = sm + buf * 4 * TILEH;
        int so = ldrow * SLD + ldseg;
        cp16h(base + so,             Ahp + (long)(m0 + ldrow) * lda + k0 + ldseg);
        cp16h(base + TILEH + so,     Alp + (long)(m0 + ldrow) * lda + k0 + ldseg);
        cp16h(base + 2*TILEH + so,   Bhp + (long)(n0 + ldrow) * ldb + k0 + ldseg);
        cp16h(base + 3*TILEH + so,   Blp + (long)(n0 + ldrow) * ldb + k0 + ldseg);
        asm volatile("cp.async.commit_group;\n");
    };

    const u32 smemU = (u32)__cvta_generic_to_shared(sm);
    const u32 laneOff = (u32)((lane & 15) * (SLD * 2) + ((lane >> 4) & 1) * 16);

    issue_loads(0, 0);
    const int nIter = K / 16;

    for (int i = 0; i < nIter; i++) {
        asm volatile("cp.async.wait_group 0;\n");
        __syncthreads();
        if (i + 1 < nIter) issue_loads((i + 1) * 16, (i + 1) & 1);

        const u32 sb = smemU + (u32)((i & 1) * 4 * TILEH * 2);
        const u32 aH = sb;
        const u32 aL = sb + TILEH * 2;
        const u32 bH = sb + 2 * TILEH * 2;
        const u32 bL = sb + 3 * TILEH * 2;

        u32 ah[4][4], al[4][4], bh[4][2], bl[4][2];
        #pragma unroll
        for (int p = 0; p < 2; p++) {
            u32 r0, r1, r2, r3;
            u32 off = (u32)((nwarp + p * 16) * (SLD * 2)) + laneOff;
            ldsm4(bH + off, r0, r1, r2, r3);
            bh[2*p][0] = r0; bh[2*p+1][0] = r1; bh[2*p][1] = r2; bh[2*p+1][1] = r3;
            ldsm4(bL + off, r0, r1, r2, r3);
            bl[2*p][0] = r0; bl[2*p+1][0] = r1; bl[2*p][1] = r2; bl[2*p+1][1] = r3;
        }
        #pragma unroll
        for (int mt = 0; mt < 4; mt++) {
            u32 off = (u32)((mwarp + mt * 16) * (SLD * 2)) + laneOff;
            ldsm4(aH + off, ah[mt][0], ah[mt][1], ah[mt][2], ah[mt][3]);
            ldsm4(aL + off, al[mt][0], al[mt][1], al[mt][2], al[mt][3]);
        }

        // term-major: 16 independent MMAs between accumulator reuses
        #pragma unroll
        for (int mt = 0; mt < 4; mt++)
            #pragma unroll
            for (int nt = 0; nt < 4; nt++)
                mma16(acc[mt * 4 + nt], ah[mt], bh[nt]);   // hi*hi
        #pragma unroll
        for (int mt = 0; mt < 4; mt++)
            #pragma unroll
            for (int nt = 0; nt < 4; nt++)
                mma16(acc[mt * 4 + nt], al[mt], bh[nt]);   // lo*hi
        #pragma unroll
        for (int mt = 0; mt < 4; mt++)
            #pragma unroll
            for (int nt = 0; nt < 4; nt++)
                mma16(acc[mt * 4 + nt], ah[mt], bl[nt]);   // hi*lo
        __syncthreads();
    }

    // ---- epilogue ----
    #pragma unroll
    for (int mt = 0; mt < 4; mt++) {
        #pragma unroll
        for (int nt = 0; nt < 4; nt++) {
            const float* a4 = acc[mt * 4 + nt];
            int rr = m0 + mwarp + mt * 16 + g;
            int cc = n0 + nwarp + nt * 8 + 2 * t;
            #pragma unroll
            for (int half = 0; half < 2; half++) {
                int m = rr + half * 8;
                float v0 = a4[half * 2 + 0] * alpha;
                float v1 = a4[half * 2 + 1] * alpha;
                if (BIAS) { v0 += bias[cc]; v1 += bias[cc + 1]; }
                if (RELU) { v0 = fmaxf(v0, 0.f); v1 = fmaxf(v1, 0.f); }
                if (RES) {
                    v0 += res[(long)m * ldr + cc];
                    v1 += res[(long)m * ldr + cc + 1];
                }
                if (F16OUT) {
                    __half h0, l0, h1, l1;
                    fsplit(v0, h0, l0); fsplit(v1, h1, l1);
                    *reinterpret_cast<__half2*>(&Ch[(long)m * ldc + cc]) = __halves2half2(h0, h1);
                    *reinterpret_cast<__half2*>(&Cl[(long)m * ldc + cc]) = __halves2half2(l0, l1);
                } else {
                    Cf[(long)m * ldc + cc]     = v0;
                    Cf[(long)m * ldc + cc + 1] = v1;
                }
            }
        }
    }
}

// ---------------- launch ----------------
extern "C" void kernel_launch(void* const* d_in, const int* in_sizes, int n_in,
                              void* d_out, int out_size)
{
    const float* x     = (const float*)d_in[0];
    const float* wq    = (const float*)d_in[1];
    const float* wk    = (const float*)d_in[2];
    const float* wv    = (const float*)d_in[3];
    const float* w1    = (const float*)d_in[4];
    const float* b1    = (const float*)d_in[5];
    const float* w2    = (const float*)d_in[6];
    const float* b2    = (const float*)d_in[7];
    const float* ln1_g = (const float*)d_in[8];
    const float* ln1_b = (const float*)d_in[9];
    const float* ln2_g = (const float*)d_in[10];
    const float* ln2_b = (const float*)d_in[11];
    float* out = (float*)d_out;

    __half *hH,*hL, *wqTH,*wqTL, *wkTH,*wkTL, *wvTH,*wvTL, *w1TH,*w1TL, *w2TH,*w2TL;
    __half *qH,*qL, *kH,*kL, *vH,*vL, *vtH,*vtL, *pH,*pL, *f1H,*f1L;
    float *sc, *xmid;
    cudaGetSymbolAddress((void**)&hH, g_hH);   cudaGetSymbolAddress((void**)&hL, g_hL);
    cudaGetSymbolAddress((void**)&wqTH, g_wqTH); cudaGetSymbolAddress((void**)&wqTL, g_wqTL);
    cudaGetSymbolAddress((void**)&wkTH, g_wkTH); cudaGetSymbolAddress((void**)&wkTL, g_wkTL);
    cudaGetSymbolAddress((void**)&wvTH, g_wvTH); cudaGetSymbolAddress((void**)&wvTL, g_wvTL);
    cudaGetSymbolAddress((void**)&w1TH, g_w1TH); cudaGetSymbolAddress((void**)&w1TL, g_w1TL);
    cudaGetSymbolAddress((void**)&w2TH, g_w2TH); cudaGetSymbolAddress((void**)&w2TL, g_w2TL);
    cudaGetSymbolAddress((void**)&qH, g_qH);   cudaGetSymbolAddress((void**)&qL, g_qL);
    cudaGetSymbolAddress((void**)&kH, g_kH);   cudaGetSymbolAddress((void**)&kL, g_kL);
    cudaGetSymbolAddress((void**)&vH, g_vH);   cudaGetSymbolAddress((void**)&vL, g_vL);
    cudaGetSymbolAddress((void**)&vtH, g_vtH); cudaGetSymbolAddress((void**)&vtL, g_vtL);
    cudaGetSymbolAddress((void**)&pH, g_pH);   cudaGetSymbolAddress((void**)&pL, g_pL);
    cudaGetSymbolAddress((void**)&f1H, g_ff1H); cudaGetSymbolAddress((void**)&f1L, g_ff1L);
    cudaGetSymbolAddress((void**)&sc, g_scores);
    cudaGetSymbolAddress((void**)&xmid, g_xmid);

    const float scale = 11.3137084989847604f;  // sqrt(128)
    const long HTD  = (long)T_ * DH_;          // per-head q/k/v
    const long BTD  = (long)H_ * HTD;          // per-b q/k/v
    const long STT  = (long)T_ * T_;
    const long SBB  = (long)H_ * STT;
    const long TC   = (long)T_ * C_;

    // ---- weight pre-pass: transpose + split to fp16 hi/lo ----
    tr_split32_kernel<<<dim3(DH_/32, C_/32, H_), 256>>>(wq, wqTH, wqTL, C_, DH_);
    tr_split32_kernel<<<dim3(DH_/32, C_/32, H_), 256>>>(wk, wkTH, wkTL, C_, DH_);
    tr_split32_kernel<<<dim3(DH_/32, C_/32, H_), 256>>>(wv, wvTH, wvTL, C_, DH_);
    tr_split32_kernel<<<dim3(DFF_/32, C_/32, 1), 256>>>(w1, w1TH, w1TL, C_, DFF_);
    tr_split32_kernel<<<dim3(C_/32, DFF_/32, 1), 256>>>(w2, w2TH, w2TL, DFF_, C_);

    // ---- LN1 ----
    ln_split_kernel<<<ROWS_, 256>>>(x, ln1_g, ln1_b, hH, hL);

    // ---- QKV: A=h [rows][C], B=w^T [Dh][C] per head ----
    dim3 gq(1, T_/128, B_*H_);
    hgemm3_kernel<false,false,false,true><<<gq, 256>>>(
        C_, hH, hL, C_, TC, 0,  wqTH, wqTL, C_, 0, (long)DH_*C_,
        nullptr, qH, qL, DH_, BTD, HTD,  nullptr, nullptr, 0, 0, 0, 1.f, H_);
    hgemm3_kernel<false,false,false,true><<<gq, 256>>>(
        C_, hH, hL, C_, TC, 0,  wkTH, wkTL, C_, 0, (long)DH_*C_,
        nullptr, kH, kL, DH_, BTD, HTD,  nullptr, nullptr, 0, 0, 0, 1.f, H_);
    hgemm3_kernel<false,false,false,true><<<gq, 256>>>(
        C_, hH, hL, C_, TC, 0,  wvTH, wvTL, C_, 0, (long)DH_*C_,
        nullptr, vH, vL, DH_, BTD, HTD,  nullptr, nullptr, 0, 0, 0, 1.f, H_);

    // ---- V^T: [T][Dh] -> [Dh][T] per (b,h) ----
    tr_pair16_kernel<<<dim3(DH_/32, T_/32, B_*H_), 256>>>(vH, vL, vtH, vtL, T_, DH_);

    // ---- scores = Q @ K^T * sqrt(Dh) (fp32 out) ----
    dim3 gs(T_/128, T_/128, B_*H_);
    hgemm3_kernel<false,false,false,false><<<gs, 256>>>(
        DH_, qH, qL, DH_, BTD, HTD,  kH, kL, DH_, BTD, HTD,
        sc, nullptr, nullptr, T_, SBB, STT,  nullptr, nullptr, 0, 0, 0, scale, H_);

    // ---- softmax -> probs hi/lo ----
    softmax_split_kernel<<<B_*H_*T_, 256>>>(sc, pH, pL);

    // ---- O = P @ V (+x residual) -> xmid fp32 ----
    dim3 go(1, T_/128, B_*H_);
    hgemm3_kernel<false,false,true,false><<<go, 256>>>(
        T_, pH, pL, T_, SBB, STT,  vtH, vtL, T_, BTD, HTD,
        xmid, nullptr, nullptr, C_, TC, DH_,  nullptr, x, C_, TC, DH_, 1.f, H_);

    // ---- LN2 ----
    ln_split_kernel<<<ROWS_, 256>>>(xmid, ln2_g, ln2_b, hH, hL);

    // ---- FF1: relu(h @ w1 + b1) -> fp16 hi/lo ----
    dim3 g1(DFF_/128, ROWS_/128, 1);
    hgemm3_kernel<true,true,false,true><<<g1, 256>>>(
        C_, hH, hL, C_, 0, 0,  w1TH, w1TL, C_, 0, 0,
        nullptr, f1H, f1L, DFF_, 0, 0,  b1, nullptr, 0, 0, 0, 1.f, 1);

    // ---- FF2: out = xmid + ff1 @ w2 + b2 (fp32) ----
    dim3 g2(C_/128, ROWS_/128, 1);
    hgemm3_kernel<false,true,true,false><<<g2, 256>>>(
        DFF_, f1H, f1L, DFF_, 0, 0,  w2TH, w2TL, DFF_, 0, 0,
        out, nullptr, nullptr, C_, 0, 0,  b2, xmid, C_, 0, 0, 1.f, 1);
}